// round 14
// baseline (speedup 1.0000x reference)
#include <cuda_runtime.h>
#include <cstdint>

#define NUM_USERS 100000
#define NUM_ITEMS 50000
#define NNODES    150000            // NUM_USERS + NUM_ITEMS
#define DIM       64
#define NEDGES    2000000
#define NUM_LAYERS 2

// ---------------------------------------------------------------------------
// Scratch: __device__ globals (allocation inside kernel_launch is forbidden).
//   g_emb  : current layer embedding        [N, 64]
//   g_next : scatter-add target             [N, 64]
//   g_acc  : running sum emb0+emb1+emb2     [N, 64]
//   g_src/g_dst : edge indices normalized to int32
// ---------------------------------------------------------------------------
__device__ float g_emb [NNODES * DIM];
__device__ float g_next[NNODES * DIM];
__device__ float g_acc [NNODES * DIM];
__device__ int   g_src [NEDGES];
__device__ int   g_dst [NEDGES];

// Vectorized no-return global atomic add (sm_90+): 1 RED.128 instead of 4 scalar atomics.
__device__ __forceinline__ void red_add_v4(float* p, float4 v) {
    asm volatile("red.global.add.v4.f32 [%0], {%1, %2, %3, %4};"
                 :: "l"(__cvta_generic_to_global(p)),
                    "f"(v.x), "f"(v.y), "f"(v.z), "f"(v.w)
                 : "memory");
}

// ---------------------------------------------------------------------------
// Edge-index normalization. Reference asks for int64, but default-config JAX
// silently produces int32. Detect the layout at runtime: for an int64 buffer
// every odd 32-bit word is 0 (indices < 150000 are positive, < 2^31).
// For int32 data the odd words are random indices; P(4 of them all zero) ~ 0.
// ---------------------------------------------------------------------------
__global__ void convert_edges_kernel(const int* __restrict__ ei_raw) {
    bool is64 = (__ldg(ei_raw + 1) == 0) & (__ldg(ei_raw + 3) == 0) &
                (__ldg(ei_raw + 5) == 0) & (__ldg(ei_raw + 7) == 0);
    int e = blockIdx.x * blockDim.x + threadIdx.x;
    if (e >= NEDGES) return;
    if (is64) {
        g_src[e] = __ldg(ei_raw + 2 * (size_t)e);
        g_dst[e] = __ldg(ei_raw + 2 * ((size_t)NEDGES + e));
    } else {
        g_src[e] = __ldg(ei_raw + e);
        g_dst[e] = __ldg(ei_raw + NEDGES + e);
    }
}

// ---------------------------------------------------------------------------
// Init: emb = acc = concat(users, items); next = 0; also emit the verbatim
// emb_users / emb_items copies the reference returns (outputs 2 and 4).
// Output float4 layout: users_final [0,1.6M) | users [1.6M,3.2M)
//                     | items_final [3.2M,4.0M) | items [4.0M,4.8M)
// ---------------------------------------------------------------------------
__global__ void init_kernel(const float4* __restrict__ users,
                            const float4* __restrict__ items,
                            float4* __restrict__ out) {
    const int U4 = NUM_USERS * DIM / 4;   // 1,600,000
    const int T4 = NNODES    * DIM / 4;   // 2,400,000
    int idx = blockIdx.x * blockDim.x + threadIdx.x;
    if (idx >= T4) return;
    float4 v = (idx < U4) ? __ldg(users + idx) : __ldg(items + (idx - U4));
    reinterpret_cast<float4*>(g_emb)[idx]  = v;
    reinterpret_cast<float4*>(g_acc)[idx]  = v;
    reinterpret_cast<float4*>(g_next)[idx] = make_float4(0.f, 0.f, 0.f, 0.f);
    if (idx < U4) out[U4 + idx] = v;                       // emb_users copy
    else          out[4000000 + (idx - U4)] = v;           // emb_items copy
}

// ---------------------------------------------------------------------------
// Scatter: 16 threads per edge, each moves one float4 of the 64-float row.
// Node table (38.4 MB) lives in L2, so gather + RED both hit L2.
// ---------------------------------------------------------------------------
__global__ void scatter_kernel(const float* __restrict__ ew) {
    unsigned gid = blockIdx.x * blockDim.x + threadIdx.x;
    int e = gid >> 4;
    if (e >= NEDGES) return;
    int t = gid & 15;
    int s = g_src[e];
    int d = g_dst[e];
    float w = __ldg(ew + e);
    float4 v = *reinterpret_cast<const float4*>(g_emb + (size_t)s * DIM + t * 4);
    v.x *= w; v.y *= w; v.z *= w; v.w *= w;
    red_add_v4(g_next + (size_t)d * DIM + t * 4, v);
}

// ---------------------------------------------------------------------------
// relu + accumulate + rotate buffers: emb = relu(next); acc += emb; next = 0.
// ---------------------------------------------------------------------------
__global__ void relu_acc_kernel() {
    const int T4 = NNODES * DIM / 4;
    int idx = blockIdx.x * blockDim.x + threadIdx.x;
    if (idx >= T4) return;
    float4 v = reinterpret_cast<float4*>(g_next)[idx];
    v.x = fmaxf(v.x, 0.f); v.y = fmaxf(v.y, 0.f);
    v.z = fmaxf(v.z, 0.f); v.w = fmaxf(v.w, 0.f);
    reinterpret_cast<float4*>(g_emb)[idx] = v;
    float4 a = reinterpret_cast<float4*>(g_acc)[idx];
    a.x += v.x; a.y += v.y; a.z += v.z; a.w += v.w;
    reinterpret_cast<float4*>(g_acc)[idx] = a;
    reinterpret_cast<float4*>(g_next)[idx] = make_float4(0.f, 0.f, 0.f, 0.f);
}

// ---------------------------------------------------------------------------
// Final: out_row = (acc_row / 3) @ W^T + b.  256 threads = 4 rows/block.
// W kept transposed in shared so lane j reads Wt[k*64+j] conflict-free;
// srow[g][k] is a warp-uniform broadcast.
// ---------------------------------------------------------------------------
__global__ void final_kernel(const float* __restrict__ W,
                             const float* __restrict__ b,
                             float* __restrict__ out) {
    __shared__ float Wt[DIM * DIM];
    __shared__ float bs[DIM];
    __shared__ float srow[4][DIM];

    int tid = threadIdx.x;
    for (int i = tid; i < DIM * DIM; i += 256) {
        int j = i >> 6, k = i & 63;
        Wt[k * DIM + j] = __ldg(W + i);          // transpose: Wt[k][j] = W[j][k]
    }
    if (tid < DIM) bs[tid] = __ldg(b + tid);

    int g = tid >> 6;          // row group within block (0..3)
    int j = tid & 63;          // output feature
    int row = blockIdx.x * 4 + g;                // grid = 37500 -> rows 0..149999
    srow[g][j] = g_acc[(size_t)row * DIM + j] * (1.0f / 3.0f);
    __syncthreads();

    float sum = bs[j];
    #pragma unroll
    for (int k = 0; k < DIM; k++)
        sum = fmaf(srow[g][k], Wt[k * DIM + j], sum);

    // users_final rows at [0, 100000), items_final rows mapped past the
    // emb_users copy: float offset (row + NUM_USERS)*64 for row >= NUM_USERS.
    size_t off = (row < NUM_USERS) ? (size_t)row * DIM
                                   : (size_t)(row + NUM_USERS) * DIM;
    out[off + j] = sum;
}

// ---------------------------------------------------------------------------
// Launch. Inputs (metadata order): edge_index (2,E) int64/int32, edge_weight
// (E,) f32, emb_users (100000,64) f32, emb_items (50000,64) f32, W (64,64),
// b (64,). Output: 19.2M f32.
// ---------------------------------------------------------------------------
extern "C" void kernel_launch(void* const* d_in, const int* in_sizes, int n_in,
                              void* d_out, int out_size) {
    const int*   ei    = (const int*)  d_in[0];   // raw words; layout probed on device
    const float* ew    = (const float*)d_in[1];
    const float* users = (const float*)d_in[2];
    const float* items = (const float*)d_in[3];
    const float* W     = (const float*)d_in[4];
    const float* b     = (const float*)d_in[5];
    float*       out   = (float*)d_out;

    convert_edges_kernel<<<(NEDGES + 255) / 256, 256>>>(ei);
    init_kernel<<<(NNODES * DIM / 4 + 255) / 256, 256>>>(
        (const float4*)users, (const float4*)items, (float4*)out);

    for (int l = 0; l < NUM_LAYERS; l++) {
        scatter_kernel<<<(NEDGES * 16) / 256, 256>>>(ew);   // 125000 blocks
        relu_acc_kernel<<<(NNODES * DIM / 4 + 255) / 256, 256>>>();
    }

    final_kernel<<<NNODES / 4, 256>>>(W, b, out);           // 37500 blocks
}

// round 15
// speedup vs baseline: 1.1437x; 1.1437x over previous
#include <cuda_runtime.h>
#include <cstdint>

#define NUM_USERS 100000
#define NUM_ITEMS 50000
#define NNODES    150000            // NUM_USERS + NUM_ITEMS
#define DIM       64
#define NEDGES    2000000
#define NUM_LAYERS 2

#define SCAN_BLK  1024
#define NB_SCAN   ((NNODES + SCAN_BLK - 1) / SCAN_BLK)   // 147

// ---------------------------------------------------------------------------
// Scratch (__device__ globals — allocation in kernel_launch is forbidden).
// ---------------------------------------------------------------------------
__device__ float g_embA[NNODES * DIM];
__device__ float g_embB[NNODES * DIM];
__device__ float g_acc [NNODES * DIM];
__device__ int   g_src [NEDGES];
__device__ int   g_dst [NEDGES];
__device__ int   g_count  [NNODES];
__device__ int   g_rowptr [NNODES + 1];
__device__ int   g_cursor [NNODES];
__device__ int   g_blocksums[NB_SCAN];
__device__ int   g_blockoff [NB_SCAN];
__device__ int2  g_csr[NEDGES];     // {src, __float_as_int(weight)} grouped by dst

// ---------------------------------------------------------------------------
// Edge-index normalization + count-array zeroing.
// Reference asks for int64 but default-JAX silently yields int32; probe the
// layout: for int64, odd 32-bit words are all zero (indices < 2^31).
// ---------------------------------------------------------------------------
__global__ void convert_edges_kernel(const int* __restrict__ ei_raw) {
    bool is64 = (__ldg(ei_raw + 1) == 0) & (__ldg(ei_raw + 3) == 0) &
                (__ldg(ei_raw + 5) == 0) & (__ldg(ei_raw + 7) == 0);
    int e = blockIdx.x * blockDim.x + threadIdx.x;
    if (e < NNODES) g_count[e] = 0;
    if (e >= NEDGES) return;
    if (is64) {
        g_src[e] = __ldg(ei_raw + 2 * (size_t)e);
        g_dst[e] = __ldg(ei_raw + 2 * ((size_t)NEDGES + e));
    } else {
        g_src[e] = __ldg(ei_raw + e);
        g_dst[e] = __ldg(ei_raw + NEDGES + e);
    }
}

// ---------------------------------------------------------------------------
// CSR build: histogram -> exclusive scan (3 kernels) -> cursor fill.
// ---------------------------------------------------------------------------
__global__ void count_kernel() {
    int e = blockIdx.x * blockDim.x + threadIdx.x;
    if (e >= NEDGES) return;
    atomicAdd(&g_count[g_dst[e]], 1);
}

__global__ void scan1_kernel() {    // per-block exclusive scan of counts
    __shared__ int sh[SCAN_BLK];
    int i = blockIdx.x * SCAN_BLK + threadIdx.x;
    int v = (i < NNODES) ? g_count[i] : 0;
    sh[threadIdx.x] = v;
    __syncthreads();
    for (int off = 1; off < SCAN_BLK; off <<= 1) {
        int t = (threadIdx.x >= off) ? sh[threadIdx.x - off] : 0;
        __syncthreads();
        sh[threadIdx.x] += t;
        __syncthreads();
    }
    int incl = sh[threadIdx.x];
    if (i < NNODES) g_rowptr[i] = incl - v;            // block-local exclusive
    if (threadIdx.x == SCAN_BLK - 1) g_blocksums[blockIdx.x] = incl;
}

__global__ void scan2_kernel() {    // exclusive scan of 147 block sums
    __shared__ int sh[256];
    int v = (threadIdx.x < NB_SCAN) ? g_blocksums[threadIdx.x] : 0;
    sh[threadIdx.x] = v;
    __syncthreads();
    for (int off = 1; off < 256; off <<= 1) {
        int t = (threadIdx.x >= off) ? sh[threadIdx.x - off] : 0;
        __syncthreads();
        sh[threadIdx.x] += t;
        __syncthreads();
    }
    if (threadIdx.x < NB_SCAN) g_blockoff[threadIdx.x] = sh[threadIdx.x] - v;
}

__global__ void scan3_kernel() {    // globalize + init cursors
    int i = blockIdx.x * blockDim.x + threadIdx.x;
    if (i >= NNODES) return;
    int v = g_rowptr[i] + g_blockoff[i >> 10];
    g_rowptr[i] = v;
    g_cursor[i] = v;
    if (i == 0) g_rowptr[NNODES] = NEDGES;
}

__global__ void fill_kernel(const float* __restrict__ ew) {
    int e = blockIdx.x * blockDim.x + threadIdx.x;
    if (e >= NEDGES) return;
    int d = g_dst[e];
    int slot = atomicAdd(&g_cursor[d], 1);
    g_csr[slot] = make_int2(g_src[e], __float_as_int(__ldg(ew + e)));
}

// ---------------------------------------------------------------------------
// Init: embA = acc = concat(users, items); also emit the verbatim
// emb_users / emb_items copies the reference returns.
// Output float4 layout: users_final [0,1.6M) | users [1.6M,3.2M)
//                     | items_final [3.2M,4.0M) | items [4.0M,4.8M)
// ---------------------------------------------------------------------------
__global__ void init_kernel(const float4* __restrict__ users,
                            const float4* __restrict__ items,
                            float4* __restrict__ out) {
    const int U4 = NUM_USERS * DIM / 4;   // 1,600,000
    const int T4 = NNODES    * DIM / 4;   // 2,400,000
    int idx = blockIdx.x * blockDim.x + threadIdx.x;
    if (idx >= T4) return;
    float4 v = (idx < U4) ? __ldg(users + idx) : __ldg(items + (idx - U4));
    reinterpret_cast<float4*>(g_embA)[idx] = v;
    reinterpret_cast<float4*>(g_acc)[idx]  = v;
    if (idx < U4) out[U4 + idx] = v;                       // emb_users copy
    else          out[4000000 + (idx - U4)] = v;           // emb_items copy
}

// ---------------------------------------------------------------------------
// SpMM + relu + acc, fused. 16 threads per node, one float4 per thread.
// No float atomics: per-node gather-reduce over the destination CSR.
// 4-way unrolled edge loop for memory-level parallelism.
// ---------------------------------------------------------------------------
template <int IN_A>
__global__ void spmm_kernel() {
    unsigned gid = blockIdx.x * blockDim.x + threadIdx.x;
    int node = gid >> 4;
    if (node >= NNODES) return;
    int t = gid & 15;

    const float* __restrict__ ein  = IN_A ? g_embA : g_embB;
    float*       __restrict__ eout = IN_A ? g_embB : g_embA;

    int beg = __ldg(&g_rowptr[node]);
    int end = __ldg(&g_rowptr[node + 1]);

    float4 s = make_float4(0.f, 0.f, 0.f, 0.f);
    int i = beg;
    for (; i + 3 < end; i += 4) {
        int2 p0 = __ldg(&g_csr[i + 0]);
        int2 p1 = __ldg(&g_csr[i + 1]);
        int2 p2 = __ldg(&g_csr[i + 2]);
        int2 p3 = __ldg(&g_csr[i + 3]);
        float4 v0 = __ldg(reinterpret_cast<const float4*>(ein + (size_t)p0.x * DIM) + t);
        float4 v1 = __ldg(reinterpret_cast<const float4*>(ein + (size_t)p1.x * DIM) + t);
        float4 v2 = __ldg(reinterpret_cast<const float4*>(ein + (size_t)p2.x * DIM) + t);
        float4 v3 = __ldg(reinterpret_cast<const float4*>(ein + (size_t)p3.x * DIM) + t);
        float w0 = __int_as_float(p0.y), w1 = __int_as_float(p1.y);
        float w2 = __int_as_float(p2.y), w3 = __int_as_float(p3.y);
        s.x = fmaf(w0, v0.x, s.x); s.y = fmaf(w0, v0.y, s.y);
        s.z = fmaf(w0, v0.z, s.z); s.w = fmaf(w0, v0.w, s.w);
        s.x = fmaf(w1, v1.x, s.x); s.y = fmaf(w1, v1.y, s.y);
        s.z = fmaf(w1, v1.z, s.z); s.w = fmaf(w1, v1.w, s.w);
        s.x = fmaf(w2, v2.x, s.x); s.y = fmaf(w2, v2.y, s.y);
        s.z = fmaf(w2, v2.z, s.z); s.w = fmaf(w2, v2.w, s.w);
        s.x = fmaf(w3, v3.x, s.x); s.y = fmaf(w3, v3.y, s.y);
        s.z = fmaf(w3, v3.z, s.z); s.w = fmaf(w3, v3.w, s.w);
    }
    for (; i < end; i++) {
        int2 p = __ldg(&g_csr[i]);
        float4 v = __ldg(reinterpret_cast<const float4*>(ein + (size_t)p.x * DIM) + t);
        float w = __int_as_float(p.y);
        s.x = fmaf(w, v.x, s.x); s.y = fmaf(w, v.y, s.y);
        s.z = fmaf(w, v.z, s.z); s.w = fmaf(w, v.w, s.w);
    }

    // relu, emit next-layer emb, accumulate into acc
    s.x = fmaxf(s.x, 0.f); s.y = fmaxf(s.y, 0.f);
    s.z = fmaxf(s.z, 0.f); s.w = fmaxf(s.w, 0.f);
    size_t o = (size_t)node * 16 + t;
    reinterpret_cast<float4*>(eout)[o] = s;
    float4 a = reinterpret_cast<float4*>(g_acc)[o];
    a.x += s.x; a.y += s.y; a.z += s.z; a.w += s.w;
    reinterpret_cast<float4*>(g_acc)[o] = a;
}

// ---------------------------------------------------------------------------
// Final: out_row = (acc_row / 3) @ W^T + b.  256 threads = 4 rows/block.
// ---------------------------------------------------------------------------
__global__ void final_kernel(const float* __restrict__ W,
                             const float* __restrict__ b,
                             float* __restrict__ out) {
    __shared__ float Wt[DIM * DIM];
    __shared__ float bs[DIM];
    __shared__ float srow[4][DIM];

    int tid = threadIdx.x;
    for (int i = tid; i < DIM * DIM; i += 256) {
        int j = i >> 6, k = i & 63;
        Wt[k * DIM + j] = __ldg(W + i);          // transpose: Wt[k][j] = W[j][k]
    }
    if (tid < DIM) bs[tid] = __ldg(b + tid);

    int g = tid >> 6;
    int j = tid & 63;
    int row = blockIdx.x * 4 + g;
    srow[g][j] = g_acc[(size_t)row * DIM + j] * (1.0f / 3.0f);
    __syncthreads();

    float sum = bs[j];
    #pragma unroll
    for (int k = 0; k < DIM; k++)
        sum = fmaf(srow[g][k], Wt[k * DIM + j], sum);

    size_t off = (row < NUM_USERS) ? (size_t)row * DIM
                                   : (size_t)(row + NUM_USERS) * DIM;
    out[off + j] = sum;
}

// ---------------------------------------------------------------------------
// Launch. Inputs (metadata order): edge_index (2,E), edge_weight (E,) f32,
// emb_users (100000,64) f32, emb_items (50000,64) f32, W (64,64), b (64,).
// ---------------------------------------------------------------------------
extern "C" void kernel_launch(void* const* d_in, const int* in_sizes, int n_in,
                              void* d_out, int out_size) {
    const int*   ei    = (const int*)  d_in[0];
    const float* ew    = (const float*)d_in[1];
    const float* users = (const float*)d_in[2];
    const float* items = (const float*)d_in[3];
    const float* W     = (const float*)d_in[4];
    const float* b     = (const float*)d_in[5];
    float*       out   = (float*)d_out;

    const int EB = (NEDGES + 255) / 256;
    const int TB = (NNODES * DIM / 4 + 255) / 256;
    const int NBn = (NNODES + 255) / 256;

    // CSR build (int atomics only; per-launch, deterministic structure)
    convert_edges_kernel<<<EB, 256>>>(ei);
    count_kernel<<<EB, 256>>>();
    scan1_kernel<<<NB_SCAN, SCAN_BLK>>>();
    scan2_kernel<<<1, 256>>>();
    scan3_kernel<<<NBn, 256>>>();
    fill_kernel<<<EB, 256>>>(ew);

    // Embedding init + verbatim input copies
    init_kernel<<<TB, 256>>>((const float4*)users, (const float4*)items,
                             (float4*)out);

    // Two propagation layers, ping-pong emb buffers, relu+acc fused
    spmm_kernel<1><<<(NNODES * 16 + 255) / 256, 256>>>();   // A -> B
    spmm_kernel<0><<<(NNODES * 16 + 255) / 256, 256>>>();   // B -> A

    final_kernel<<<NNODES / 4, 256>>>(W, b, out);
}

// round 16
// speedup vs baseline: 2.7616x; 2.4146x over previous
#include <cuda_runtime.h>
#include <cstdint>

#define NUM_USERS 100000
#define NUM_ITEMS 50000
#define NNODES    150000            // NUM_USERS + NUM_ITEMS
#define DIM       64
#define NEDGES    2000000

#define SCAN_NBLK     19
#define SCAN_THREADS  1024
#define SCAN_ITEMS    8
#define SCAN_CHUNK    (SCAN_THREADS * SCAN_ITEMS)   // 8192; 19*8192 >= 150000

// ---------------------------------------------------------------------------
// Scratch (__device__ globals — allocation in kernel_launch is forbidden).
// Invariants maintained across calls (needed for graph replay determinism):
//   g_count : all zero on entry  (module-load zero-init; scan re-zeroes)
//   g_flag  : all zero on entry  (module-load zero-init; fill re-zeroes)
// ---------------------------------------------------------------------------
__device__ float g_embA[NNODES * DIM];
__device__ float g_embB[NNODES * DIM];
__device__ float g_acc [NNODES * DIM];
__device__ int   g_src [NEDGES];
__device__ int   g_dst [NEDGES];
__device__ int   g_count [NNODES];
__device__ int   g_rowptr[NNODES + 1];
__device__ int   g_cursor[NNODES];
__device__ int   g_flag  [SCAN_NBLK];
__device__ int2  g_csr[NEDGES];     // {src, __float_as_int(weight)} grouped by dst

// ---------------------------------------------------------------------------
// Launch 1: init emb/acc + verbatim input copies + edge convert + degree count.
// Edge-index dtype probe: reference asks int64 but default-JAX yields int32;
// for int64 every odd 32-bit word is 0 (indices < 2^31 and positive).
// Output float4 layout: users_final [0,1.6M) | users [1.6M,3.2M)
//                     | items_final [3.2M,4.0M) | items [4.0M,4.8M)
// ---------------------------------------------------------------------------
__global__ void fused_init_kernel(const int* __restrict__ ei,
                                  const float4* __restrict__ users,
                                  const float4* __restrict__ items,
                                  float4* __restrict__ out) {
    const int U4 = NUM_USERS * DIM / 4;   // 1,600,000
    const int T4 = NNODES    * DIM / 4;   // 2,400,000
    int idx = blockIdx.x * blockDim.x + threadIdx.x;

    if (idx < T4) {
        float4 v = (idx < U4) ? __ldg(users + idx) : __ldg(items + (idx - U4));
        reinterpret_cast<float4*>(g_embA)[idx] = v;
        reinterpret_cast<float4*>(g_acc)[idx]  = v;
        if (idx < U4) __stcs(out + U4 + idx, v);              // emb_users copy
        else          __stcs(out + 4000000 + (idx - U4), v);  // emb_items copy
    }

    if (idx < NEDGES) {
        bool is64 = (__ldg(ei + 1) == 0) & (__ldg(ei + 3) == 0) &
                    (__ldg(ei + 5) == 0) & (__ldg(ei + 7) == 0);
        int s, d;
        if (is64) {
            int2 ps = __ldg(reinterpret_cast<const int2*>(ei) + idx);
            int2 pd = __ldg(reinterpret_cast<const int2*>(ei) + NEDGES + idx);
            s = ps.x; d = pd.x;
        } else {
            s = __ldg(ei + idx);
            d = __ldg(ei + NEDGES + idx);
        }
        g_src[idx] = s;
        g_dst[idx] = d;
        atomicAdd(&g_count[d], 1);       // g_count zero on entry (invariant)
    }
}

// ---------------------------------------------------------------------------
// Launch 2: single-kernel chained exclusive scan of g_count -> rowptr/cursor.
// 19 blocks, all resident simultaneously (19 << 148 SMs) so the flag chain
// cannot deadlock. Published value is prefix+1 so flag==0 means "not ready"
// (matches the zero-initialized / fill-reset state). Re-zeroes g_count.
// ---------------------------------------------------------------------------
__global__ void scan_kernel() {
    __shared__ int stot[SCAN_THREADS];
    __shared__ int s_base;
    int tid = threadIdx.x, bid = blockIdx.x;
    int base = bid * SCAN_CHUNK + tid * SCAN_ITEMS;

    int v[SCAN_ITEMS];
    int sum = 0;
    #pragma unroll
    for (int k = 0; k < SCAN_ITEMS; k++) {
        int i = base + k;
        v[k] = (i < NNODES) ? g_count[i] : 0;
        sum += v[k];
    }
    stot[tid] = sum;
    __syncthreads();
    for (int off = 1; off < SCAN_THREADS; off <<= 1) {
        int t = (tid >= off) ? stot[tid - off] : 0;
        __syncthreads();
        stot[tid] += t;
        __syncthreads();
    }
    int thr_excl = stot[tid] - sum;
    int btot = stot[SCAN_THREADS - 1];

    if (tid == 0) {
        int prev = 0;
        if (bid > 0) {
            int f;
            do { f = atomicAdd(&g_flag[bid - 1], 0); } while (f == 0);
            prev = f - 1;
        }
        atomicExch(&g_flag[bid], prev + btot + 1);
        s_base = prev;
    }
    __syncthreads();

    int off0 = s_base + thr_excl;
    #pragma unroll
    for (int k = 0; k < SCAN_ITEMS; k++) {
        int i = base + k;
        if (i < NNODES) {
            g_rowptr[i] = off0;
            g_cursor[i] = off0;
            g_count[i]  = 0;             // restore invariant for next call
        }
        off0 += v[k];
    }
    if (bid == SCAN_NBLK - 1 && tid == SCAN_THREADS - 1)
        g_rowptr[NNODES] = NEDGES;
}

// ---------------------------------------------------------------------------
// Launch 3: CSR fill (int atomics on 150K spread cursors) + flag reset.
// ---------------------------------------------------------------------------
__global__ void fill_kernel(const float* __restrict__ ew) {
    if (blockIdx.x == 0 && threadIdx.x < SCAN_NBLK)
        g_flag[threadIdx.x] = 0;         // restore invariant (scan already done)
    int e = blockIdx.x * blockDim.x + threadIdx.x;
    if (e >= NEDGES) return;
    int d = g_dst[e];
    int slot = atomicAdd(&g_cursor[d], 1);
    g_csr[slot] = make_int2(g_src[e], __float_as_int(__ldg(ew + e)));
}

// ---------------------------------------------------------------------------
// Launches 4+5: SpMM + relu + acc, fused. 16 threads/node, one float4 each.
// Per-node gather-reduce over destination CSR; zero float atomics.
// ---------------------------------------------------------------------------
template <int IN_A>
__global__ void spmm_kernel() {
    unsigned gid = blockIdx.x * blockDim.x + threadIdx.x;
    int node = gid >> 4;
    if (node >= NNODES) return;
    int t = gid & 15;

    const float* __restrict__ ein  = IN_A ? g_embA : g_embB;
    float*       __restrict__ eout = IN_A ? g_embB : g_embA;

    int beg = __ldg(&g_rowptr[node]);
    int end = __ldg(&g_rowptr[node + 1]);

    float4 s = make_float4(0.f, 0.f, 0.f, 0.f);
    int i = beg;
    for (; i + 3 < end; i += 4) {
        int2 p0 = __ldg(&g_csr[i + 0]);
        int2 p1 = __ldg(&g_csr[i + 1]);
        int2 p2 = __ldg(&g_csr[i + 2]);
        int2 p3 = __ldg(&g_csr[i + 3]);
        float4 v0 = __ldg(reinterpret_cast<const float4*>(ein + (size_t)p0.x * DIM) + t);
        float4 v1 = __ldg(reinterpret_cast<const float4*>(ein + (size_t)p1.x * DIM) + t);
        float4 v2 = __ldg(reinterpret_cast<const float4*>(ein + (size_t)p2.x * DIM) + t);
        float4 v3 = __ldg(reinterpret_cast<const float4*>(ein + (size_t)p3.x * DIM) + t);
        float w0 = __int_as_float(p0.y), w1 = __int_as_float(p1.y);
        float w2 = __int_as_float(p2.y), w3 = __int_as_float(p3.y);
        s.x = fmaf(w0, v0.x, s.x); s.y = fmaf(w0, v0.y, s.y);
        s.z = fmaf(w0, v0.z, s.z); s.w = fmaf(w0, v0.w, s.w);
        s.x = fmaf(w1, v1.x, s.x); s.y = fmaf(w1, v1.y, s.y);
        s.z = fmaf(w1, v1.z, s.z); s.w = fmaf(w1, v1.w, s.w);
        s.x = fmaf(w2, v2.x, s.x); s.y = fmaf(w2, v2.y, s.y);
        s.z = fmaf(w2, v2.z, s.z); s.w = fmaf(w2, v2.w, s.w);
        s.x = fmaf(w3, v3.x, s.x); s.y = fmaf(w3, v3.y, s.y);
        s.z = fmaf(w3, v3.z, s.z); s.w = fmaf(w3, v3.w, s.w);
    }
    for (; i < end; i++) {
        int2 p = __ldg(&g_csr[i]);
        float4 v = __ldg(reinterpret_cast<const float4*>(ein + (size_t)p.x * DIM) + t);
        float w = __int_as_float(p.y);
        s.x = fmaf(w, v.x, s.x); s.y = fmaf(w, v.y, s.y);
        s.z = fmaf(w, v.z, s.z); s.w = fmaf(w, v.w, s.w);
    }

    s.x = fmaxf(s.x, 0.f); s.y = fmaxf(s.y, 0.f);
    s.z = fmaxf(s.z, 0.f); s.w = fmaxf(s.w, 0.f);
    size_t o = (size_t)node * 16 + t;
    reinterpret_cast<float4*>(eout)[o] = s;
    float4 a = reinterpret_cast<float4*>(g_acc)[o];
    a.x += s.x; a.y += s.y; a.z += s.z; a.w += s.w;
    reinterpret_cast<float4*>(g_acc)[o] = a;
}

// ---------------------------------------------------------------------------
// Launch 6: out_row = (acc_row / 3) @ W^T + b. Block-persistent: each block
// loads W once (16KB smem) and loops over ~32 row-groups -> W L2 traffic
// drops from 600MB (37500 loads) to ~19MB (1184 loads).
// ---------------------------------------------------------------------------
__global__ void final_kernel(const float* __restrict__ W,
                             const float* __restrict__ b,
                             float* __restrict__ out) {
    __shared__ float Wt[DIM * DIM];
    __shared__ float bs[DIM];
    __shared__ float srow[4][DIM];

    int tid = threadIdx.x;
    for (int i = tid; i < DIM * DIM; i += 256) {
        int j = i >> 6, k = i & 63;
        Wt[k * DIM + j] = __ldg(W + i);          // Wt[k][j] = W[j][k]
    }
    if (tid < DIM) bs[tid] = __ldg(b + tid);

    int g = tid >> 6;
    int j = tid & 63;

    for (int grp = blockIdx.x; grp < NNODES / 4; grp += gridDim.x) {
        int row = grp * 4 + g;
        __syncthreads();                         // Wt/bs ready; prior reads done
        srow[g][j] = g_acc[(size_t)row * DIM + j] * (1.0f / 3.0f);
        __syncthreads();
        float sum = bs[j];
        #pragma unroll
        for (int k = 0; k < DIM; k++)
            sum = fmaf(srow[g][k], Wt[k * DIM + j], sum);
        size_t off = (row < NUM_USERS) ? (size_t)row * DIM
                                       : (size_t)(row + NUM_USERS) * DIM;
        __stcs(out + off + j, sum);
    }
}

// ---------------------------------------------------------------------------
// Launch. Inputs (metadata order): edge_index (2,E), edge_weight (E,) f32,
// emb_users (100000,64) f32, emb_items (50000,64) f32, W (64,64), b (64,).
// 6 launches total; launch #4 (profiled by the harness's ncu capture) is
// spmm_kernel<1>.
// ---------------------------------------------------------------------------
extern "C" void kernel_launch(void* const* d_in, const int* in_sizes, int n_in,
                              void* d_out, int out_size) {
    const int*   ei    = (const int*)  d_in[0];
    const float* ew    = (const float*)d_in[1];
    const float* users = (const float*)d_in[2];
    const float* items = (const float*)d_in[3];
    const float* W     = (const float*)d_in[4];
    const float* b     = (const float*)d_in[5];
    float*       out   = (float*)d_out;

    const int T4 = NNODES * DIM / 4;                       // 2.4M (covers NEDGES too)

    fused_init_kernel<<<(T4 + 255) / 256, 256>>>(
        ei, (const float4*)users, (const float4*)items, (float4*)out); // 1
    scan_kernel<<<SCAN_NBLK, SCAN_THREADS>>>();                        // 2
    fill_kernel<<<(NEDGES + 255) / 256, 256>>>(ew);                    // 3
    spmm_kernel<1><<<(NNODES * 16 + 255) / 256, 256>>>();              // 4 (profiled)
    spmm_kernel<0><<<(NNODES * 16 + 255) / 256, 256>>>();              // 5
    final_kernel<<<1184, 256>>>(W, b, out);                            // 6
}